// round 2
// baseline (speedup 1.0000x reference)
#include <cuda_runtime.h>
#include <math.h>

// Problem constants
#define BATCH   8
#define TLEN    2048
#define CDIM    1024
#define HDIM    64
#define BT      (BATCH * TLEN)   // 16384 rows

// Scratch for projected Q, K, V (12 MB total) — __device__ globals per harness rules
__device__ float g_Q[BT * HDIM];
__device__ float g_K[BT * HDIM];
__device__ float g_V[BT * HDIM];

// ----------------------------------------------------------------------------
// Kernel 1: fused QKV projection.
// Each block computes a 64-row slab of all three projections (x tile loaded
// once, reused for Wq/Wk/Wv). 256 threads in a 16x16 layout; each thread owns
// a 4-row x 4-col x 3-matrix register tile (48 accumulators).
// ----------------------------------------------------------------------------
__global__ __launch_bounds__(256) void qkv_proj(
    const float* __restrict__ x,
    const float* __restrict__ Wq,
    const float* __restrict__ Wk,
    const float* __restrict__ Wv)
{
    __shared__ float xs[16][64];        // [kk][row] (transposed for row-contig reads)
    __shared__ float ws[3][16][64];     // [mat][kk][col]

    const int tid = threadIdx.x;
    const int tx  = tid & 15;           // col group
    const int ty  = tid >> 4;           // row group
    const int rowBase = blockIdx.x * 64;

    float acc[3][4][4] = {};

    for (int k0 = 0; k0 < CDIM; k0 += 16) {
        // Load x tile: 64 rows x 16 k, stored transposed as xs[kk][row]
        {
            const int r   = tid >> 2;            // 0..63
            const int kk4 = (tid & 3) * 4;       // 0,4,8,12
            const float4 v = *(const float4*)&x[(size_t)(rowBase + r) * CDIM + k0 + kk4];
            xs[kk4 + 0][r] = v.x;
            xs[kk4 + 1][r] = v.y;
            xs[kk4 + 2][r] = v.z;
            xs[kk4 + 3][r] = v.w;
        }
        // Load W tiles: 16 k x 64 cols each
        {
            const int kk = tid >> 4;             // 0..15
            const int c4 = (tid & 15) * 4;       // 0..60
            *(float4*)&ws[0][kk][c4] = *(const float4*)&Wq[(size_t)(k0 + kk) * HDIM + c4];
            *(float4*)&ws[1][kk][c4] = *(const float4*)&Wk[(size_t)(k0 + kk) * HDIM + c4];
            *(float4*)&ws[2][kk][c4] = *(const float4*)&Wv[(size_t)(k0 + kk) * HDIM + c4];
        }
        __syncthreads();

        #pragma unroll
        for (int kk = 0; kk < 16; kk++) {
            const float4 a4 = *(const float4*)&xs[kk][ty * 4];
            const float a[4] = {a4.x, a4.y, a4.z, a4.w};
            #pragma unroll
            for (int m = 0; m < 3; m++) {
                const float4 b4 = *(const float4*)&ws[m][kk][tx * 4];
                const float b[4] = {b4.x, b4.y, b4.z, b4.w};
                #pragma unroll
                for (int r = 0; r < 4; r++)
                    #pragma unroll
                    for (int c = 0; c < 4; c++)
                        acc[m][r][c] += a[r] * b[c];
            }
        }
        __syncthreads();
    }

    // Write out (float4 per matrix per row)
    #pragma unroll
    for (int r = 0; r < 4; r++) {
        const int row = rowBase + ty * 4 + r;
        const int col = tx * 4;
        float4 q4 = {acc[0][r][0], acc[0][r][1], acc[0][r][2], acc[0][r][3]};
        float4 k4 = {acc[1][r][0], acc[1][r][1], acc[1][r][2], acc[1][r][3]};
        float4 v4 = {acc[2][r][0], acc[2][r][1], acc[2][r][2], acc[2][r][3]};
        *(float4*)&g_Q[(size_t)row * HDIM + col] = q4;
        *(float4*)&g_K[(size_t)row * HDIM + col] = k4;
        *(float4*)&g_V[(size_t)row * HDIM + col] = v4;
    }
}

// ----------------------------------------------------------------------------
// Kernel 2: causal flash attention (fp32, online softmax, single pass).
// Grid: (T/64, B). Each block owns a 64-query tile, iterates key tiles
// 0..qtile. 256 threads, 16x16 layout; thread tile = 4 rows x 4 dims.
// Smem: qs/ks/vs/ps, each 64 x 68 floats (PAD=68 keeps strided accesses
// conflict-free and 16B-aligned).
// ----------------------------------------------------------------------------
#define PAD 68
#define ATTN_SMEM (4 * 64 * PAD * sizeof(float))   // 69632 bytes

__global__ __launch_bounds__(256) void attn_kernel(float* __restrict__ out)
{
    extern __shared__ float smem[];
    float* qs = smem;
    float* ks = qs + 64 * PAD;
    float* vs = ks + 64 * PAD;
    float* ps = vs + 64 * PAD;

    const int qt  = blockIdx.x;          // query tile 0..31
    const int b   = blockIdx.y;          // batch
    const int tid = threadIdx.x;
    const int tx  = tid & 15;            // col/dim group
    const int ty  = tid >> 4;            // row group
    const float scale = 0.125f;          // 1/sqrt(64)

    // Load Q tile (pre-scaled)
    {
        const float* Qb = g_Q + (size_t)(b * TLEN + qt * 64) * HDIM;
        #pragma unroll
        for (int i = tid; i < 1024; i += 256) {      // 1024 float4 slots
            const int r  = i >> 4;
            const int c4 = (i & 15) * 4;
            float4 v = *(const float4*)&Qb[r * HDIM + c4];
            v.x *= scale; v.y *= scale; v.z *= scale; v.w *= scale;
            *(float4*)&qs[r * PAD + c4] = v;
        }
    }

    float m_i[4], l_i[4], acc[4][4];
    #pragma unroll
    for (int r = 0; r < 4; r++) {
        m_i[r] = -1e30f;
        l_i[r] = 0.0f;
        #pragma unroll
        for (int c = 0; c < 4; c++) acc[r][c] = 0.0f;
    }
    __syncthreads();

    for (int kt = 0; kt <= qt; kt++) {
        // Load K and V tiles
        {
            const float* Kb = g_K + (size_t)(b * TLEN + kt * 64) * HDIM;
            const float* Vb = g_V + (size_t)(b * TLEN + kt * 64) * HDIM;
            #pragma unroll
            for (int i = tid; i < 1024; i += 256) {
                const int r  = i >> 4;
                const int c4 = (i & 15) * 4;
                *(float4*)&ks[r * PAD + c4] = *(const float4*)&Kb[r * HDIM + c4];
                *(float4*)&vs[r * PAD + c4] = *(const float4*)&Vb[r * HDIM + c4];
            }
        }
        __syncthreads();

        // Scores: s[r][c] = (q_row . k_col) (q pre-scaled)
        float s[4][4] = {};
        #pragma unroll
        for (int d = 0; d < HDIM; d += 4) {
            float4 q4[4], k4[4];
            #pragma unroll
            for (int r = 0; r < 4; r++) q4[r] = *(const float4*)&qs[(ty * 4 + r) * PAD + d];
            #pragma unroll
            for (int c = 0; c < 4; c++) k4[c] = *(const float4*)&ks[(tx * 4 + c) * PAD + d];
            #pragma unroll
            for (int r = 0; r < 4; r++)
                #pragma unroll
                for (int c = 0; c < 4; c++) {
                    s[r][c] += q4[r].x * k4[c].x;
                    s[r][c] += q4[r].y * k4[c].y;
                    s[r][c] += q4[r].z * k4[c].z;
                    s[r][c] += q4[r].w * k4[c].w;
                }
        }

        // Causal mask on the diagonal tile
        if (kt == qt) {
            #pragma unroll
            for (int r = 0; r < 4; r++)
                #pragma unroll
                for (int c = 0; c < 4; c++)
                    if (tx * 4 + c > ty * 4 + r) s[r][c] = -1e30f;
        }

        // Online softmax update (row reductions across the 16 tx lanes)
        #pragma unroll
        for (int r = 0; r < 4; r++) {
            float mx = fmaxf(fmaxf(s[r][0], s[r][1]), fmaxf(s[r][2], s[r][3]));
            #pragma unroll
            for (int o = 8; o >= 1; o >>= 1)
                mx = fmaxf(mx, __shfl_xor_sync(0xffffffffu, mx, o));
            const float mnew = fmaxf(m_i[r], mx);

            float sum = 0.0f;
            #pragma unroll
            for (int c = 0; c < 4; c++) {
                s[r][c] = __expf(s[r][c] - mnew);
                sum += s[r][c];
            }
            #pragma unroll
            for (int o = 8; o >= 1; o >>= 1)
                sum += __shfl_xor_sync(0xffffffffu, sum, o);

            const float corr = __expf(m_i[r] - mnew);
            l_i[r] = l_i[r] * corr + sum;
            #pragma unroll
            for (int c = 0; c < 4; c++) acc[r][c] *= corr;
            m_i[r] = mnew;
        }

        // Stage P into shared for the PV matmul
        #pragma unroll
        for (int r = 0; r < 4; r++)
            *(float4*)&ps[(ty * 4 + r) * PAD + tx * 4] =
                make_float4(s[r][0], s[r][1], s[r][2], s[r][3]);
        __syncthreads();

        // O += P . V   (thread: 4 rows x 4 dims)
        #pragma unroll
        for (int j = 0; j < 64; j += 4) {
            float4 p4[4], vv[4];
            #pragma unroll
            for (int r = 0; r < 4; r++) p4[r] = *(const float4*)&ps[(ty * 4 + r) * PAD + j];
            #pragma unroll
            for (int jj = 0; jj < 4; jj++) vv[jj] = *(const float4*)&vs[(j + jj) * PAD + tx * 4];
            #pragma unroll
            for (int r = 0; r < 4; r++) {
                acc[r][0] += p4[r].x * vv[0].x + p4[r].y * vv[1].x + p4[r].z * vv[2].x + p4[r].w * vv[3].x;
                acc[r][1] += p4[r].x * vv[0].y + p4[r].y * vv[1].y + p4[r].z * vv[2].y + p4[r].w * vv[3].y;
                acc[r][2] += p4[r].x * vv[0].z + p4[r].y * vv[1].z + p4[r].z * vv[2].z + p4[r].w * vv[3].z;
                acc[r][3] += p4[r].x * vv[0].w + p4[r].y * vv[1].w + p4[r].z * vv[2].w + p4[r].w * vv[3].w;
            }
        }
        __syncthreads();   // before next tile overwrites ks/vs/ps
    }

    // Epilogue: out = acc / l
    float* Ob = out + (size_t)(b * TLEN + qt * 64) * HDIM;
    #pragma unroll
    for (int r = 0; r < 4; r++) {
        const float inv = 1.0f / l_i[r];
        float4 o4 = {acc[r][0] * inv, acc[r][1] * inv, acc[r][2] * inv, acc[r][3] * inv};
        *(float4*)&Ob[(ty * 4 + r) * HDIM + tx * 4] = o4;
    }
}

// ----------------------------------------------------------------------------
// Harness entry
// ----------------------------------------------------------------------------
extern "C" void kernel_launch(void* const* d_in, const int* in_sizes, int n_in,
                              void* d_out, int out_size)
{
    const float* x  = (const float*)d_in[0];
    const float* Wq = (const float*)d_in[1];
    const float* Wk = (const float*)d_in[2];
    const float* Wv = (const float*)d_in[3];
    float* out = (float*)d_out;

    (void)in_sizes; (void)n_in; (void)out_size;

    // Projection: 256 blocks x 256 threads, each block = 64 rows of Q|K|V
    qkv_proj<<<BT / 64, 256>>>(x, Wq, Wk, Wv);

    // Attention: (T/64, B) blocks, 69632 B dynamic smem (needs opt-in)
    cudaFuncSetAttribute(attn_kernel, cudaFuncAttributeMaxDynamicSharedMemorySize,
                         (int)ATTN_SMEM);
    attn_kernel<<<dim3(TLEN / 64, BATCH), 256, ATTN_SMEM>>>(out);
}

// round 3
// speedup vs baseline: 1.5110x; 1.5110x over previous
#include <cuda_runtime.h>
#include <math.h>

// Problem constants
#define BATCH   8
#define TLEN    2048
#define CDIM    1024
#define HDIM    64
#define BT      (BATCH * TLEN)   // 16384 rows

#define QTILES   32              // 64-row query tiles per batch
#define CHUNK    8               // key-tiles per attention block (split-K)
#define MAXSPLIT 4               // ceil(32 / CHUNK)

// Scratch (__device__ globals per harness rules)
__device__ float g_Q[BT * HDIM];
__device__ float g_K[BT * HDIM];
__device__ float g_V[BT * HDIM];
// Split-K partials: [b][qt][split][64 rows][64 cols], plus per-row m/l
__device__ float g_Op[BATCH * QTILES * MAXSPLIT * 64 * 64];
__device__ float g_pm[BATCH * QTILES * MAXSPLIT * 64];
__device__ float g_pl[BATCH * QTILES * MAXSPLIT * 64];

// ---------------------------------------------------------------------------
// f32x2 packed-FMA helpers (SASS FFMA2; exact fp32, 2 FMAs per issue slot)
// ---------------------------------------------------------------------------
__device__ __forceinline__ unsigned long long dup2(float a) {
    unsigned long long r;
    asm("mov.b64 %0, {%1, %1};" : "=l"(r) : "f"(a));
    return r;
}
__device__ __forceinline__ void ffma2(unsigned long long& acc,
                                      unsigned long long a,
                                      unsigned long long b) {
    asm("fma.rn.f32x2 %0, %1, %2, %0;" : "+l"(acc) : "l"(a), "l"(b));
}
__device__ __forceinline__ float2 unpack2(unsigned long long v) {
    float lo, hi;
    asm("mov.b64 {%0, %1}, %2;" : "=f"(lo), "=f"(hi) : "l"(v));
    return make_float2(lo, hi);
}

// ----------------------------------------------------------------------------
// Kernel 1: fused QKV projection with packed f32x2 FMAs.
// Block = 64-row slab of Q|K|V. 256 threads (16x16); thread tile = 4 rows x
// 4 cols x 3 matrices, accumulated as 2 packed col-pairs per matrix-row.
// ----------------------------------------------------------------------------
__global__ __launch_bounds__(256) void qkv_proj(
    const float* __restrict__ x,
    const float* __restrict__ Wq,
    const float* __restrict__ Wk,
    const float* __restrict__ Wv)
{
    __shared__ float xs[16][64];        // [kk][row]
    __shared__ float ws[3][16][64];     // [mat][kk][col]

    const int tid = threadIdx.x;
    const int tx  = tid & 15;
    const int ty  = tid >> 4;
    const int rowBase = blockIdx.x * 64;

    unsigned long long acc2[3][4][2];   // [mat][row][colpair], packed fp32 pairs
    #pragma unroll
    for (int m = 0; m < 3; m++)
        #pragma unroll
        for (int r = 0; r < 4; r++) {
            acc2[m][r][0] = 0ULL;
            acc2[m][r][1] = 0ULL;
        }

    for (int k0 = 0; k0 < CDIM; k0 += 16) {
        {
            const int r   = tid >> 2;
            const int kk4 = (tid & 3) * 4;
            const float4 v = *(const float4*)&x[(size_t)(rowBase + r) * CDIM + k0 + kk4];
            xs[kk4 + 0][r] = v.x;
            xs[kk4 + 1][r] = v.y;
            xs[kk4 + 2][r] = v.z;
            xs[kk4 + 3][r] = v.w;
        }
        {
            const int kk = tid >> 4;
            const int c4 = (tid & 15) * 4;
            *(float4*)&ws[0][kk][c4] = *(const float4*)&Wq[(size_t)(k0 + kk) * HDIM + c4];
            *(float4*)&ws[1][kk][c4] = *(const float4*)&Wk[(size_t)(k0 + kk) * HDIM + c4];
            *(float4*)&ws[2][kk][c4] = *(const float4*)&Wv[(size_t)(k0 + kk) * HDIM + c4];
        }
        __syncthreads();

        #pragma unroll
        for (int kk = 0; kk < 16; kk++) {
            const float4 a4 = *(const float4*)&xs[kk][ty * 4];
            unsigned long long ad[4];
            ad[0] = dup2(a4.x); ad[1] = dup2(a4.y);
            ad[2] = dup2(a4.z); ad[3] = dup2(a4.w);
            #pragma unroll
            for (int m = 0; m < 3; m++) {
                // ws row is 16B-aligned at tx*4: load 4 cols as 2 packed pairs
                const ulonglong2 b2 = *(const ulonglong2*)&ws[m][kk][tx * 4];
                #pragma unroll
                for (int r = 0; r < 4; r++) {
                    ffma2(acc2[m][r][0], ad[r], b2.x);
                    ffma2(acc2[m][r][1], ad[r], b2.y);
                }
            }
        }
        __syncthreads();
    }

    #pragma unroll
    for (int r = 0; r < 4; r++) {
        const int row = rowBase + ty * 4 + r;
        const int col = tx * 4;
        float2 qlo = unpack2(acc2[0][r][0]), qhi = unpack2(acc2[0][r][1]);
        float2 klo = unpack2(acc2[1][r][0]), khi = unpack2(acc2[1][r][1]);
        float2 vlo = unpack2(acc2[2][r][0]), vhi = unpack2(acc2[2][r][1]);
        *(float4*)&g_Q[(size_t)row * HDIM + col] = make_float4(qlo.x, qlo.y, qhi.x, qhi.y);
        *(float4*)&g_K[(size_t)row * HDIM + col] = make_float4(klo.x, klo.y, khi.x, khi.y);
        *(float4*)&g_V[(size_t)row * HDIM + col] = make_float4(vlo.x, vlo.y, vhi.x, vhi.y);
    }
}

// ----------------------------------------------------------------------------
// Kernel 2: causal flash attention, split-K balanced.
// Grid: (80, B). Linear id 0..79 maps to (qt, split): q-tile qt has
// ceil((qt+1)/CHUNK) = (qt>>3)+1 splits of <= CHUNK key-tiles each.
// Block writes UNNORMALIZED partial acc + per-row (m, l) to scratch.
// ----------------------------------------------------------------------------
#define PAD 68
#define ATTN_SMEM (4 * 64 * PAD * sizeof(float))   // 69632 bytes

__global__ __launch_bounds__(256) void attn_kernel()
{
    extern __shared__ float smem[];
    float* qs = smem;
    float* ks = qs + 64 * PAD;
    float* vs = ks + 64 * PAD;
    float* ps = vs + 64 * PAD;

    // Map linear block id -> (qt, split)
    int lin = blockIdx.x;
    int qt = 0;
    while (true) {
        const int S = (qt >> 3) + 1;
        if (lin < S) break;
        lin -= S;
        qt++;
    }
    const int sp  = lin;
    const int kt0 = sp * CHUNK;
    const int kt1 = min(kt0 + CHUNK, qt + 1);

    const int b   = blockIdx.y;
    const int tid = threadIdx.x;
    const int tx  = tid & 15;
    const int ty  = tid >> 4;
    const float scale = 0.125f;          // 1/sqrt(64)

    // Load Q tile (pre-scaled)
    {
        const float* Qb = g_Q + (size_t)(b * TLEN + qt * 64) * HDIM;
        #pragma unroll
        for (int i = tid; i < 1024; i += 256) {
            const int r  = i >> 4;
            const int c4 = (i & 15) * 4;
            float4 v = *(const float4*)&Qb[r * HDIM + c4];
            v.x *= scale; v.y *= scale; v.z *= scale; v.w *= scale;
            *(float4*)&qs[r * PAD + c4] = v;
        }
    }

    float m_i[4], l_i[4], acc[4][4];
    #pragma unroll
    for (int r = 0; r < 4; r++) {
        m_i[r] = -1e30f;
        l_i[r] = 0.0f;
        #pragma unroll
        for (int c = 0; c < 4; c++) acc[r][c] = 0.0f;
    }
    __syncthreads();

    for (int kt = kt0; kt < kt1; kt++) {
        {
            const float* Kb = g_K + (size_t)(b * TLEN + kt * 64) * HDIM;
            const float* Vb = g_V + (size_t)(b * TLEN + kt * 64) * HDIM;
            #pragma unroll
            for (int i = tid; i < 1024; i += 256) {
                const int r  = i >> 4;
                const int c4 = (i & 15) * 4;
                *(float4*)&ks[r * PAD + c4] = *(const float4*)&Kb[r * HDIM + c4];
                *(float4*)&vs[r * PAD + c4] = *(const float4*)&Vb[r * HDIM + c4];
            }
        }
        __syncthreads();

        // Scores
        float s[4][4] = {};
        #pragma unroll
        for (int d = 0; d < HDIM; d += 4) {
            float4 q4[4], k4[4];
            #pragma unroll
            for (int r = 0; r < 4; r++) q4[r] = *(const float4*)&qs[(ty * 4 + r) * PAD + d];
            #pragma unroll
            for (int c = 0; c < 4; c++) k4[c] = *(const float4*)&ks[(tx * 4 + c) * PAD + d];
            #pragma unroll
            for (int r = 0; r < 4; r++)
                #pragma unroll
                for (int c = 0; c < 4; c++) {
                    s[r][c] += q4[r].x * k4[c].x;
                    s[r][c] += q4[r].y * k4[c].y;
                    s[r][c] += q4[r].z * k4[c].z;
                    s[r][c] += q4[r].w * k4[c].w;
                }
        }

        // Causal mask on the diagonal tile
        if (kt == qt) {
            #pragma unroll
            for (int r = 0; r < 4; r++)
                #pragma unroll
                for (int c = 0; c < 4; c++)
                    if (tx * 4 + c > ty * 4 + r) s[r][c] = -1e30f;
        }

        // Online softmax update
        #pragma unroll
        for (int r = 0; r < 4; r++) {
            float mx = fmaxf(fmaxf(s[r][0], s[r][1]), fmaxf(s[r][2], s[r][3]));
            #pragma unroll
            for (int o = 8; o >= 1; o >>= 1)
                mx = fmaxf(mx, __shfl_xor_sync(0xffffffffu, mx, o));
            const float mnew = fmaxf(m_i[r], mx);

            float sum = 0.0f;
            #pragma unroll
            for (int c = 0; c < 4; c++) {
                s[r][c] = __expf(s[r][c] - mnew);
                sum += s[r][c];
            }
            #pragma unroll
            for (int o = 8; o >= 1; o >>= 1)
                sum += __shfl_xor_sync(0xffffffffu, sum, o);

            const float corr = __expf(m_i[r] - mnew);
            l_i[r] = l_i[r] * corr + sum;
            #pragma unroll
            for (int c = 0; c < 4; c++) acc[r][c] *= corr;
            m_i[r] = mnew;
        }

        // Stage P to shared
        #pragma unroll
        for (int r = 0; r < 4; r++)
            *(float4*)&ps[(ty * 4 + r) * PAD + tx * 4] =
                make_float4(s[r][0], s[r][1], s[r][2], s[r][3]);
        __syncthreads();

        // O += P . V
        #pragma unroll
        for (int j = 0; j < 64; j += 4) {
            float4 p4[4], vv[4];
            #pragma unroll
            for (int r = 0; r < 4; r++) p4[r] = *(const float4*)&ps[(ty * 4 + r) * PAD + j];
            #pragma unroll
            for (int jj = 0; jj < 4; jj++) vv[jj] = *(const float4*)&vs[(j + jj) * PAD + tx * 4];
            #pragma unroll
            for (int r = 0; r < 4; r++) {
                acc[r][0] += p4[r].x * vv[0].x + p4[r].y * vv[1].x + p4[r].z * vv[2].x + p4[r].w * vv[3].x;
                acc[r][1] += p4[r].x * vv[0].y + p4[r].y * vv[1].y + p4[r].z * vv[2].y + p4[r].w * vv[3].y;
                acc[r][2] += p4[r].x * vv[0].z + p4[r].y * vv[1].z + p4[r].z * vv[2].z + p4[r].w * vv[3].z;
                acc[r][3] += p4[r].x * vv[0].w + p4[r].y * vv[1].w + p4[r].z * vv[2].w + p4[r].w * vv[3].w;
            }
        }
        __syncthreads();
    }

    // Write unnormalized partials + (m, l)
    const size_t pbase = (size_t)((b * QTILES + qt) * MAXSPLIT + sp);
    float* Ob = g_Op + pbase * 4096;
    #pragma unroll
    for (int r = 0; r < 4; r++) {
        *(float4*)&Ob[(ty * 4 + r) * 64 + tx * 4] =
            make_float4(acc[r][0], acc[r][1], acc[r][2], acc[r][3]);
    }
    if (tx == 0) {
        #pragma unroll
        for (int r = 0; r < 4; r++) {
            g_pm[pbase * 64 + ty * 4 + r] = m_i[r];
            g_pl[pbase * 64 + ty * 4 + r] = l_i[r];
        }
    }
}

// ----------------------------------------------------------------------------
// Kernel 3: combine split-K partials: out = sum_s Op_s * exp(m_s - m*) / l*
// Grid: (QTILES, B), 256 threads, thread tile 4 rows x 4 cols.
// ----------------------------------------------------------------------------
__global__ __launch_bounds__(256) void attn_combine(float* __restrict__ out)
{
    const int qt  = blockIdx.x;
    const int b   = blockIdx.y;
    const int S   = (qt >> 3) + 1;
    const int tid = threadIdx.x;
    const int tx  = tid & 15;
    const int ty  = tid >> 4;

    const size_t base = (size_t)(b * QTILES + qt) * MAXSPLIT;
    float* Ob = out + (size_t)(b * TLEN + qt * 64) * HDIM;

    #pragma unroll
    for (int r = 0; r < 4; r++) {
        const int row = ty * 4 + r;

        float ms[MAXSPLIT], ls[MAXSPLIT];
        float mstar = -1e30f;
        for (int s = 0; s < S; s++) {
            ms[s] = g_pm[(base + s) * 64 + row];
            ls[s] = g_pl[(base + s) * 64 + row];
            mstar = fmaxf(mstar, ms[s]);
        }
        float lstar = 0.0f;
        float sc[MAXSPLIT];
        for (int s = 0; s < S; s++) {
            sc[s] = __expf(ms[s] - mstar);
            lstar += ls[s] * sc[s];
        }
        const float inv = 1.0f / lstar;

        float4 o = make_float4(0.f, 0.f, 0.f, 0.f);
        for (int s = 0; s < S; s++) {
            const float4 p = *(const float4*)&g_Op[(base + s) * 4096 + row * 64 + tx * 4];
            o.x += p.x * sc[s];
            o.y += p.y * sc[s];
            o.z += p.z * sc[s];
            o.w += p.w * sc[s];
        }
        o.x *= inv; o.y *= inv; o.z *= inv; o.w *= inv;
        *(float4*)&Ob[row * HDIM + tx * 4] = o;
    }
}

// ----------------------------------------------------------------------------
// Harness entry
// ----------------------------------------------------------------------------
extern "C" void kernel_launch(void* const* d_in, const int* in_sizes, int n_in,
                              void* d_out, int out_size)
{
    const float* x  = (const float*)d_in[0];
    const float* Wq = (const float*)d_in[1];
    const float* Wk = (const float*)d_in[2];
    const float* Wv = (const float*)d_in[3];
    float* out = (float*)d_out;

    (void)in_sizes; (void)n_in; (void)out_size;

    qkv_proj<<<BT / 64, 256>>>(x, Wq, Wk, Wv);

    cudaFuncSetAttribute(attn_kernel, cudaFuncAttributeMaxDynamicSharedMemorySize,
                         (int)ATTN_SMEM);
    // 80 blocks per batch: sum over qt of ceil((qt+1)/CHUNK) = 8+16+24+32
    attn_kernel<<<dim3(80, BATCH), 256, ATTN_SMEM>>>();

    attn_combine<<<dim3(QTILES, BATCH), 256>>>(out);
}